// round 8
// baseline (speedup 1.0000x reference)
#include <cuda_runtime.h>
#include <cstdint>
#include <cstddef>

// Flash attention, B=4 H=16 S=2048 D=64, fp32 in/out, tf32 mma.sync compute.
// R4: 32 query rows per warp (BM=128) to amortize smem fragment traffic.
// R5: resubmit (infra failure); removed static guard in kernel_launch.

#define LOG2E 1.4426950408889634f

constexpr int Bb = 4, Hh = 16, Ss = 2048, Dd = 64;
constexpr int BM = 128;  // query rows per CTA (32 per warp, 2 m-tiles)
constexpr int BN = 64;   // key rows per iteration
constexpr int KW = 68;   // sK stride words (stride = 4 banks: conflict-free ldsm)
constexpr int VW = 72;   // sV stride words (stride = 8 banks: conflict-free PV B)
constexpr int PW = 68;   // sP stride words

constexpr int SV_OFF = 64 * KW;            // after sK
constexpr int SP_OFF = SV_OFF + 64 * VW;   // after sV
constexpr int SMEM_WORDS = SP_OFF + BM * PW;
constexpr int SMEM_BYTES = SMEM_WORDS * 4; // 70656

__device__ __forceinline__ uint32_t f2tf(float x) {
    uint32_t r;
    asm("cvt.rna.tf32.f32 %0, %1;" : "=r"(r) : "f"(x));
    return r;
}

__device__ __forceinline__ void mma_tf32(float c[4], uint32_t a0, uint32_t a1,
                                         uint32_t a2, uint32_t a3,
                                         uint32_t b0, uint32_t b1) {
    asm volatile(
        "mma.sync.aligned.m16n8k8.row.col.f32.tf32.tf32.f32 "
        "{%0,%1,%2,%3}, {%4,%5,%6,%7}, {%8,%9}, {%0,%1,%2,%3};"
        : "+f"(c[0]), "+f"(c[1]), "+f"(c[2]), "+f"(c[3])
        : "r"(a0), "r"(a1), "r"(a2), "r"(a3), "r"(b0), "r"(b1));
}

__device__ __forceinline__ void ldsm4(uint32_t& r0, uint32_t& r1, uint32_t& r2,
                                      uint32_t& r3, uint32_t addr) {
    asm volatile(
        "ldmatrix.sync.aligned.m8n8.x4.shared.b16 {%0,%1,%2,%3}, [%4];"
        : "=r"(r0), "=r"(r1), "=r"(r2), "=r"(r3)
        : "r"(addr));
}

__global__ __launch_bounds__(128, 2) void fattn_tf32(
    const float* __restrict__ Q, const float* __restrict__ K,
    const float* __restrict__ V, float* __restrict__ O) {
    extern __shared__ uint32_t smem[];
    uint32_t* sK = smem;
    uint32_t* sV = smem + SV_OFF;
    uint32_t* sP = smem + SP_OFF;

    const int tid = threadIdx.x;
    const int warp = tid >> 5, lane = tid & 31;
    const int qg = lane >> 2;   // fragment row group
    const int tg = lane & 3;    // thread-in-group
    const int bh = blockIdx.y;
    const int m_blk = blockIdx.x * BM;

    const float* qp = Q + (size_t)bh * Ss * Dd;
    const float* kp = K + (size_t)bh * Ss * Dd;
    const float* vp = V + (size_t)bh * Ss * Dd;
    float* op = O + (size_t)bh * Ss * Dd;

    // ---- ldmatrix lane geometry ----
    const int lm_m = lane >> 3, lm_r = lane & 7;
    const uint32_t sk_base = (uint32_t)__cvta_generic_to_shared(sK);
    const uint32_t sp_base = (uint32_t)__cvta_generic_to_shared(sP);
    // QK B: matrices (n-block = 2p + (m>>1), col-half = m&1), rows = keys.
    uint32_t qk_addr[4];
#pragma unroll
    for (int p = 0; p < 4; p++) {
        const int krow = (2 * p + (lm_m >> 1)) * 8 + lm_r;
        qk_addr[p] = sk_base + (uint32_t)((krow * KW + (lm_m & 1) * 4) * 4);
    }
    // aP per m-tile: A fragment of this warp's 16 rows (mt*16 offset).
    uint32_t ap_addr[2];
#pragma unroll
    for (int mt = 0; mt < 2; mt++) {
        const int prow = warp * 32 + mt * 16 + (lm_m >> 1) * 8 + lm_r;
        ap_addr[mt] = sp_base + (uint32_t)((prow * PW + (lm_m & 1) * 4) * 4);
    }

    // ---- Q fragments (2 m-tiles), pre-scaled by 1/8 (exact in tf32) ----
    uint32_t aQ[2][8][4];
#pragma unroll
    for (int mt = 0; mt < 2; mt++) {
        const int r0 = m_blk + warp * 32 + mt * 16 + qg;
#pragma unroll
        for (int k = 0; k < 8; k++) {
            const int c0 = k * 8 + tg;
            aQ[mt][k][0] = f2tf(qp[(size_t)r0 * Dd + c0] * 0.125f);
            aQ[mt][k][1] = f2tf(qp[(size_t)(r0 + 8) * Dd + c0] * 0.125f);
            aQ[mt][k][2] = f2tf(qp[(size_t)r0 * Dd + c0 + 4] * 0.125f);
            aQ[mt][k][3] = f2tf(qp[(size_t)(r0 + 8) * Dd + c0 + 4] * 0.125f);
        }
    }

    float Oc[2][8][4];
#pragma unroll
    for (int mt = 0; mt < 2; mt++)
#pragma unroll
        for (int n = 0; n < 8; n++)
#pragma unroll
            for (int j = 0; j < 4; j++) Oc[mt][n][j] = 0.f;
    float mrow[2][2] = {{-1e30f, -1e30f}, {-1e30f, -1e30f}};
    float lrow[2][2] = {{0.f, 0.f}, {0.f, 0.f}};

    const int ldr = tid / 16;         // staging row base
    const int ldc = (tid % 16) * 4;   // staging col (words)

    for (int kb = 0; kb < Ss / BN; kb++) {
        __syncthreads();  // prior iteration's K/V reads complete

        // ---- stage K,V tiles (fp32 -> tf32 on store) ----
        const float* kg = kp + (size_t)kb * BN * Dd;
        const float* vg = vp + (size_t)kb * BN * Dd;
#pragma unroll
        for (int rr = 0; rr < 8; rr++) {
            const int r = ldr + rr * 8;
            float4 kf = *(const float4*)(kg + r * Dd + ldc);
            float4 vf = *(const float4*)(vg + r * Dd + ldc);
            uint4 ku = make_uint4(f2tf(kf.x), f2tf(kf.y), f2tf(kf.z), f2tf(kf.w));
            uint4 vu = make_uint4(f2tf(vf.x), f2tf(vf.y), f2tf(vf.z), f2tf(vf.w));
            *(uint4*)(sK + r * KW + ldc) = ku;
            *(uint4*)(sV + r * VW + ldc) = vu;
        }
        __syncthreads();

        // ---- per m-tile: S = (Q/8) K^T, softmax, P store (own rows only) ----
#pragma unroll
        for (int mt = 0; mt < 2; mt++) {
            float sc[8][4];
#pragma unroll
            for (int n = 0; n < 8; n++)
                sc[n][0] = sc[n][1] = sc[n][2] = sc[n][3] = 0.f;
#pragma unroll
            for (int k = 0; k < 8; k++) {
#pragma unroll
                for (int p = 0; p < 4; p++) {
                    uint32_t b0, b1, b2, b3;
                    ldsm4(b0, b1, b2, b3, qk_addr[p] + (uint32_t)(k * 32));
                    mma_tf32(sc[2 * p], aQ[mt][k][0], aQ[mt][k][1],
                             aQ[mt][k][2], aQ[mt][k][3], b0, b1);
                    mma_tf32(sc[2 * p + 1], aQ[mt][k][0], aQ[mt][k][1],
                             aQ[mt][k][2], aQ[mt][k][3], b2, b3);
                }
            }

            // online softmax (two row-halves per thread)
            float mx0 = sc[0][0], mx1 = sc[0][2];
#pragma unroll
            for (int n = 0; n < 8; n++) {
                mx0 = fmaxf(mx0, fmaxf(sc[n][0], sc[n][1]));
                mx1 = fmaxf(mx1, fmaxf(sc[n][2], sc[n][3]));
            }
#pragma unroll
            for (int h = 1; h < 4; h <<= 1) {
                mx0 = fmaxf(mx0, __shfl_xor_sync(0xffffffffu, mx0, h));
                mx1 = fmaxf(mx1, __shfl_xor_sync(0xffffffffu, mx1, h));
            }
            const float mn0 = fmaxf(mrow[mt][0], mx0);
            const float mn1 = fmaxf(mrow[mt][1], mx1);
            const float al0 = exp2f((mrow[mt][0] - mn0) * LOG2E);
            const float al1 = exp2f((mrow[mt][1] - mn1) * LOG2E);
            mrow[mt][0] = mn0;
            mrow[mt][1] = mn1;
            float rs0 = 0.f, rs1 = 0.f;
#pragma unroll
            for (int n = 0; n < 8; n++) {
                sc[n][0] = exp2f((sc[n][0] - mn0) * LOG2E);
                sc[n][1] = exp2f((sc[n][1] - mn0) * LOG2E);
                sc[n][2] = exp2f((sc[n][2] - mn1) * LOG2E);
                sc[n][3] = exp2f((sc[n][3] - mn1) * LOG2E);
                rs0 += sc[n][0] + sc[n][1];
                rs1 += sc[n][2] + sc[n][3];
                Oc[mt][n][0] *= al0;
                Oc[mt][n][1] *= al0;
                Oc[mt][n][2] *= al1;
                Oc[mt][n][3] *= al1;
            }
            lrow[mt][0] = lrow[mt][0] * al0 + rs0;
            lrow[mt][1] = lrow[mt][1] * al1 + rs1;

            // store P into this warp's private sP rows
            const int prow0 = warp * 32 + mt * 16 + qg;
            uint32_t* pr0 = sP + prow0 * PW + 2 * tg;
            uint32_t* pr1 = sP + (prow0 + 8) * PW + 2 * tg;
#pragma unroll
            for (int n = 0; n < 8; n++) {
                uint2 lo = make_uint2(f2tf(sc[n][0]), f2tf(sc[n][1]));
                uint2 hi = make_uint2(f2tf(sc[n][2]), f2tf(sc[n][3]));
                *(uint2*)(pr0 + n * 8) = lo;
                *(uint2*)(pr1 + n * 8) = hi;
            }
        }
        __syncwarp();

        // ---- O += P V : V B-fragments shared across both m-tiles ----
        const uint32_t* vb = sV + tg * VW + qg;
#pragma unroll
        for (int k = 0; k < 8; k++) {
            uint32_t p0[4], p1[4];
            ldsm4(p0[0], p0[1], p0[2], p0[3], ap_addr[0] + (uint32_t)(k * 32));
            ldsm4(p1[0], p1[1], p1[2], p1[3], ap_addr[1] + (uint32_t)(k * 32));
            // ldsm returns {a0, a2, a1, a3}
#pragma unroll
            for (int n = 0; n < 8; n++) {
                uint32_t b0 = vb[k * 8 * VW + n * 8];
                uint32_t b1 = vb[(k * 8 + 4) * VW + n * 8];
                mma_tf32(Oc[0][n], p0[0], p0[2], p0[1], p0[3], b0, b1);
                mma_tf32(Oc[1][n], p1[0], p1[2], p1[1], p1[3], b0, b1);
            }
        }
    }

    // ---- epilogue: finish l reduction, normalize, write ----
#pragma unroll
    for (int mt = 0; mt < 2; mt++) {
        float l0 = lrow[mt][0], l1 = lrow[mt][1];
#pragma unroll
        for (int h = 1; h < 4; h <<= 1) {
            l0 += __shfl_xor_sync(0xffffffffu, l0, h);
            l1 += __shfl_xor_sync(0xffffffffu, l1, h);
        }
        const float inv0 = 1.f / l0;
        const float inv1 = 1.f / l1;
        const int r0 = m_blk + warp * 32 + mt * 16 + qg;
#pragma unroll
        for (int n = 0; n < 8; n++) {
            op[(size_t)r0 * Dd + n * 8 + 2 * tg]       = Oc[mt][n][0] * inv0;
            op[(size_t)r0 * Dd + n * 8 + 2 * tg + 1]   = Oc[mt][n][1] * inv0;
            op[(size_t)(r0 + 8) * Dd + n * 8 + 2 * tg]     = Oc[mt][n][2] * inv1;
            op[(size_t)(r0 + 8) * Dd + n * 8 + 2 * tg + 1] = Oc[mt][n][3] * inv1;
        }
    }
}

extern "C" void kernel_launch(void* const* d_in, const int* in_sizes, int n_in,
                              void* d_out, int out_size) {
    const float* Q = (const float*)d_in[0];
    const float* K = (const float*)d_in[1];
    const float* V = (const float*)d_in[2];
    float* O = (float*)d_out;
    cudaFuncSetAttribute(fattn_tf32,
                         cudaFuncAttributeMaxDynamicSharedMemorySize,
                         SMEM_BYTES);
    dim3 grid(Ss / BM, Bb * Hh);
    fattn_tf32<<<grid, 128, SMEM_BYTES>>>(Q, K, V, O);
}